// round 1
// baseline (speedup 1.0000x reference)
#include <cuda_runtime.h>
#include <cuda_bf16.h>
#include <cstdint>

// Problem constants
#define BB 2
#define HH 16
#define SS 2048
#define DKK 64
#define SCALE 0.125f   // 1/sqrt(64)

typedef unsigned long long ULL;

// ---------- packed f32x2 helpers (2x fp32 FMA throughput on sm_103a) ----------
__device__ __forceinline__ ULL pack2(float lo, float hi) {
    ULL r;
    asm("mov.b64 %0, {%1, %2};" : "=l"(r) : "f"(lo), "f"(hi));
    return r;
}
__device__ __forceinline__ void unpack2(ULL v, float& lo, float& hi) {
    asm("mov.b64 {%0, %1}, %2;" : "=f"(lo), "=f"(hi) : "l"(v));
}
__device__ __forceinline__ ULL ffma2(ULL a, ULL b, ULL c) {
    ULL d;
    asm("fma.rn.f32x2 %0, %1, %2, %3;" : "=l"(d) : "l"(a), "l"(b), "l"(c));
    return d;
}

// Fallback scratch in case the harness output holds only `output` (not the tuple).
__device__ float g_attn_scratch[(size_t)BB * HH * SS * SS];

// ============================================================================
// Kernel 1: scores[bh,q,k] = mask ? dot(Q[bh,q,:], K[bh,k,:]) * scale : -1e9
// 64x64 output tile per CTA, DK=64 fully staged in smem (transposed, padded).
// ============================================================================
__global__ __launch_bounds__(256)
void qk_kernel(const float* __restrict__ Q, const float* __restrict__ K,
               const int* __restrict__ mask, float* __restrict__ attn) {
    __shared__ float QsT[64][68];   // [d][q], row stride 68 floats (16B aligned)
    __shared__ float KsT[64][68];   // [d][k]

    const int bh = blockIdx.z;
    const int b  = bh >> 4;         // H = 16
    const int q0 = blockIdx.y * 64;
    const int k0 = blockIdx.x * 64;
    const int tid = threadIdx.x;

    const float* Qp = Q + ((size_t)bh * SS + q0) * DKK;
    const float* Kp = K + ((size_t)bh * SS + k0) * DKK;

    // Cooperative load + transpose: 64 rows x 16 float4 each matrix
#pragma unroll
    for (int r = 0; r < 4; ++r) {
        int idx = tid + r * 256;        // 0..1023
        int row = idx >> 4;             // 0..63
        int d4  = idx & 15;             // 0..15
        float4 qv = ((const float4*)(Qp + (size_t)row * DKK))[d4];
        float4 kv = ((const float4*)(Kp + (size_t)row * DKK))[d4];
        QsT[4 * d4 + 0][row] = qv.x; QsT[4 * d4 + 1][row] = qv.y;
        QsT[4 * d4 + 2][row] = qv.z; QsT[4 * d4 + 3][row] = qv.w;
        KsT[4 * d4 + 0][row] = kv.x; KsT[4 * d4 + 1][row] = kv.y;
        KsT[4 * d4 + 2][row] = kv.z; KsT[4 * d4 + 3][row] = kv.w;
    }
    __syncthreads();

    const int tx = tid & 15;   // k micro-tile (4 cols)
    const int ty = tid >> 4;   // q micro-tile (4 rows)

    ULL acc[4][2];
#pragma unroll
    for (int i = 0; i < 4; ++i) { acc[i][0] = 0ULL; acc[i][1] = 0ULL; }

#pragma unroll 16
    for (int kk = 0; kk < 64; ++kk) {
        float4 a = *(const float4*)&QsT[kk][ty * 4];
        float4 bv = *(const float4*)&KsT[kk][tx * 4];
        ULL bp0 = pack2(bv.x, bv.y);
        ULL bp1 = pack2(bv.z, bv.w);
        ULL ap;
        ap = pack2(a.x, a.x);
        acc[0][0] = ffma2(ap, bp0, acc[0][0]); acc[0][1] = ffma2(ap, bp1, acc[0][1]);
        ap = pack2(a.y, a.y);
        acc[1][0] = ffma2(ap, bp0, acc[1][0]); acc[1][1] = ffma2(ap, bp1, acc[1][1]);
        ap = pack2(a.z, a.z);
        acc[2][0] = ffma2(ap, bp0, acc[2][0]); acc[2][1] = ffma2(ap, bp1, acc[2][1]);
        ap = pack2(a.w, a.w);
        acc[3][0] = ffma2(ap, bp0, acc[3][0]); acc[3][1] = ffma2(ap, bp1, acc[3][1]);
    }

    // Epilogue: scale, mask, store
    float* outp = attn + ((size_t)bh * SS + q0) * SS + k0;
    const int* mrow = mask + ((size_t)b * SS + q0) * SS + k0;

#pragma unroll
    for (int i = 0; i < 4; ++i) {
        int q = ty * 4 + i;
        float r0, r1, r2, r3;
        unpack2(acc[i][0], r0, r1);
        unpack2(acc[i][1], r2, r3);
        int4 mk = *(const int4*)&mrow[(size_t)q * SS + tx * 4];
        float4 v;
        v.x = (mk.x == 0) ? -1e9f : r0 * SCALE;
        v.y = (mk.y == 0) ? -1e9f : r1 * SCALE;
        v.z = (mk.z == 0) ? -1e9f : r2 * SCALE;
        v.w = (mk.w == 0) ? -1e9f : r3 * SCALE;
        *(float4*)&outp[(size_t)q * SS + tx * 4] = v;
    }
}

// ============================================================================
// Kernel 2: in-place row softmax over 2048 elements. One CTA (128 thr) / row.
// ============================================================================
__global__ __launch_bounds__(128)
void softmax_kernel(float* __restrict__ attn) {
    const size_t row = blockIdx.x;
    float* p = attn + row * (size_t)SS;
    const int tid = threadIdx.x;

    float4 v[4];
#pragma unroll
    for (int t = 0; t < 4; ++t) v[t] = ((const float4*)p)[tid + t * 128];

    float m = -3.4e38f;
#pragma unroll
    for (int t = 0; t < 4; ++t)
        m = fmaxf(m, fmaxf(fmaxf(v[t].x, v[t].y), fmaxf(v[t].z, v[t].w)));

#pragma unroll
    for (int o = 16; o > 0; o >>= 1)
        m = fmaxf(m, __shfl_xor_sync(0xffffffffu, m, o));

    __shared__ float redm[4];
    __shared__ float reds[4];
    const int wid = tid >> 5, lid = tid & 31;
    if (lid == 0) redm[wid] = m;
    __syncthreads();
    m = fmaxf(fmaxf(redm[0], redm[1]), fmaxf(redm[2], redm[3]));

    float s = 0.f;
#pragma unroll
    for (int t = 0; t < 4; ++t) {
        v[t].x = __expf(v[t].x - m); v[t].y = __expf(v[t].y - m);
        v[t].z = __expf(v[t].z - m); v[t].w = __expf(v[t].w - m);
        s += (v[t].x + v[t].y) + (v[t].z + v[t].w);
    }
#pragma unroll
    for (int o = 16; o > 0; o >>= 1)
        s += __shfl_xor_sync(0xffffffffu, s, o);
    if (lid == 0) reds[wid] = s;
    __syncthreads();
    s = (reds[0] + reds[1]) + (reds[2] + reds[3]);

    const float inv = 1.0f / s;
#pragma unroll
    for (int t = 0; t < 4; ++t) {
        v[t].x *= inv; v[t].y *= inv; v[t].z *= inv; v[t].w *= inv;
        ((float4*)p)[tid + t * 128] = v[t];
    }
}

// ============================================================================
// Kernel 3: O[bh,q,:] = sum_k W[bh,q,k] * V[bh,k,:]. 64q x 64d tile per CTA,
// k-loop in steps of 32 through smem.
// ============================================================================
__global__ __launch_bounds__(256)
void pv_kernel(const float* __restrict__ attn, const float* __restrict__ V,
               float* __restrict__ O) {
    __shared__ float WsT[32][68];  // [k][q]
    __shared__ float Vs[32][68];   // [k][d]

    const int bh = blockIdx.y;
    const int q0 = blockIdx.x * 64;
    const int tid = threadIdx.x;
    const int tx = tid & 15;   // d micro-tile
    const int ty = tid >> 4;   // q micro-tile

    const float* Wp = attn + ((size_t)bh * SS + q0) * SS;
    const float* Vp = V + (size_t)bh * SS * DKK;

    ULL acc[4][2];
#pragma unroll
    for (int i = 0; i < 4; ++i) { acc[i][0] = 0ULL; acc[i][1] = 0ULL; }

    for (int kt = 0; kt < SS / 32; ++kt) {
        // W tile: 64 q-rows x 32 k (512 float4), transpose into WsT[k][q]
#pragma unroll
        for (int r = 0; r < 2; ++r) {
            int idx = tid + r * 256;     // 0..511
            int row = idx >> 3;          // q: 0..63
            int c4  = idx & 7;           // k float4: 0..7
            float4 w = ((const float4*)(Wp + (size_t)row * SS + kt * 32))[c4];
            WsT[4 * c4 + 0][row] = w.x; WsT[4 * c4 + 1][row] = w.y;
            WsT[4 * c4 + 2][row] = w.z; WsT[4 * c4 + 3][row] = w.w;
        }
        // V tile: 32 k-rows x 64 d (512 float4), natural layout
#pragma unroll
        for (int r = 0; r < 2; ++r) {
            int idx = tid + r * 256;
            int row = idx >> 4;          // k: 0..31
            int d4  = idx & 15;          // d float4: 0..15
            float4 vv = ((const float4*)(Vp + (size_t)(kt * 32 + row) * DKK))[d4];
            *(float4*)&Vs[row][d4 * 4] = vv;
        }
        __syncthreads();

#pragma unroll 16
        for (int kk = 0; kk < 32; ++kk) {
            float4 a = *(const float4*)&WsT[kk][ty * 4];
            float4 bv = *(const float4*)&Vs[kk][tx * 4];
            ULL bp0 = pack2(bv.x, bv.y);
            ULL bp1 = pack2(bv.z, bv.w);
            ULL ap;
            ap = pack2(a.x, a.x);
            acc[0][0] = ffma2(ap, bp0, acc[0][0]); acc[0][1] = ffma2(ap, bp1, acc[0][1]);
            ap = pack2(a.y, a.y);
            acc[1][0] = ffma2(ap, bp0, acc[1][0]); acc[1][1] = ffma2(ap, bp1, acc[1][1]);
            ap = pack2(a.z, a.z);
            acc[2][0] = ffma2(ap, bp0, acc[2][0]); acc[2][1] = ffma2(ap, bp1, acc[2][1]);
            ap = pack2(a.w, a.w);
            acc[3][0] = ffma2(ap, bp0, acc[3][0]); acc[3][1] = ffma2(ap, bp1, acc[3][1]);
        }
        __syncthreads();
    }

#pragma unroll
    for (int i = 0; i < 4; ++i) {
        int q = ty * 4 + i;
        float r0, r1, r2, r3;
        unpack2(acc[i][0], r0, r1);
        unpack2(acc[i][1], r2, r3);
        float4 v = make_float4(r0, r1, r2, r3);
        *(float4*)&O[((size_t)bh * SS + q0 + q) * DKK + tx * 4] = v;
    }
}

// ============================================================================
// Launch
// ============================================================================
extern "C" void kernel_launch(void* const* d_in, const int* in_sizes, int n_in,
                              void* d_out, int out_size) {
    const float* Q    = (const float*)d_in[0];
    const float* K    = (const float*)d_in[1];
    const float* V    = (const float*)d_in[2];
    const int*   mask = (const int*)d_in[3];

    float* out = (float*)d_out;

    const long long O_ELEMS = (long long)BB * HH * SS * DKK;       // 4,194,304
    const long long A_ELEMS = (long long)BB * HH * SS * (long long)SS;

    float* Optr = out;
    float* attn;
    if ((long long)out_size >= O_ELEMS + A_ELEMS) {
        attn = out + O_ELEMS;   // weights are part of the output tuple
    } else {
        // output-only layout: use device scratch for the weights
        void* sp = nullptr;
        cudaGetSymbolAddress(&sp, g_attn_scratch);
        attn = (float*)sp;
    }

    dim3 g1(SS / 64, SS / 64, BB * HH);
    qk_kernel<<<g1, 256>>>(Q, K, mask, attn);

    softmax_kernel<<<(unsigned)(BB * HH * SS), 128>>>(attn);

    dim3 g3(SS / 64, BB * HH);
    pv_kernel<<<g3, 256>>>(attn, V, Optr);
}

// round 11
// speedup vs baseline: 1.8113x; 1.8113x over previous
#include <cuda_runtime.h>
#include <cuda_bf16.h>
#include <cstdint>

#define BB 2
#define HH 16
#define SS 2048
#define DKK 64
#define SCALE 0.125f   // 1/sqrt(64)
#define KP 192         // split-precision concat depth for QK

typedef unsigned int U32;
typedef unsigned long long ULL;

// ---------------------------------------------------------------------------
// helpers
// ---------------------------------------------------------------------------
__device__ __forceinline__ U32 smem_u32(const void* p) {
    U32 a;
    asm("{ .reg .u64 t; cvta.to.shared.u64 t, %1; cvt.u32.u64 %0, t; }" : "=r"(a) : "l"(p));
    return a;
}

__device__ __forceinline__ void ldsm_x4(U32* r, U32 addr) {
    asm volatile("ldmatrix.sync.aligned.m8n8.x4.shared.b16 {%0,%1,%2,%3}, [%4];"
                 : "=r"(r[0]), "=r"(r[1]), "=r"(r[2]), "=r"(r[3]) : "r"(addr));
}
__device__ __forceinline__ void ldsm_x4_t(U32* r, U32 addr) {
    asm volatile("ldmatrix.sync.aligned.m8n8.x4.trans.shared.b16 {%0,%1,%2,%3}, [%4];"
                 : "=r"(r[0]), "=r"(r[1]), "=r"(r[2]), "=r"(r[3]) : "r"(addr));
}

// D += A * B, m16n8k16, bf16 inputs, fp32 accum
__device__ __forceinline__ void mma16816(float* d, const U32* a, const U32* b) {
    asm volatile(
        "mma.sync.aligned.m16n8k16.row.col.f32.bf16.bf16.f32 "
        "{%0,%1,%2,%3}, {%4,%5,%6,%7}, {%8,%9}, {%0,%1,%2,%3};"
        : "+f"(d[0]), "+f"(d[1]), "+f"(d[2]), "+f"(d[3])
        : "r"(a[0]), "r"(a[1]), "r"(a[2]), "r"(a[3]), "r"(b[0]), "r"(b[1]));
}

// pack two fp32 -> bf16x2 (x0 in low half, x1 in high half)
__device__ __forceinline__ U32 packbf(float x0, float x1) {
    U32 r;
    asm("cvt.rn.bf16x2.f32 %0, %1, %2;" : "=r"(r) : "f"(x1), "f"(x0));
    return r;
}
__device__ __forceinline__ float bfhi(float x) {
    return __bfloat162float(__float2bfloat16(x));
}

// ---------------------------------------------------------------------------
// device scratch
// ---------------------------------------------------------------------------
__device__ float g_attn_scratch[(size_t)BB * HH * SS * SS];
__device__ __nv_bfloat16 g_qcat[(size_t)BB * HH * SS * KP];  // [hi | lo | hi]
__device__ __nv_bfloat16 g_kcat[(size_t)BB * HH * SS * KP];  // [hi | hi | lo]
__device__ __nv_bfloat16 g_vhi[(size_t)BB * HH * SS * DKK];
__device__ __nv_bfloat16 g_vlo[(size_t)BB * HH * SS * DKK];

// ============================================================================
// Prepass A: split fp32 rows (64) into bf16 blocks, K'=192 concat layout.
// mode 0: [hi | lo | hi]  (Q)      mode 1: [hi | hi | lo]  (K)
// ============================================================================
__global__ __launch_bounds__(256)
void split_kernel(const float* __restrict__ src, __nv_bfloat16* __restrict__ dst, int mode) {
    int idx = blockIdx.x * blockDim.x + threadIdx.x;   // 0 .. 65536*4-1
    int row = idx >> 2;
    int c16 = idx & 3;
    if (row >= BB * HH * SS) return;

    const float4* s = (const float4*)(src + (size_t)row * DKK + c16 * 16);
    U32 hi[8], lo[8];
#pragma unroll
    for (int i = 0; i < 4; ++i) {
        float4 v = s[i];
        float f[4] = {v.x, v.y, v.z, v.w};
#pragma unroll
        for (int j = 0; j < 2; ++j) {
            float a = f[2 * j], b = f[2 * j + 1];
            float ah = bfhi(a), bh = bfhi(b);
            hi[i * 2 + j] = packbf(ah, bh);
            lo[i * 2 + j] = packbf(a - ah, b - bh);
        }
    }
    U32* o = (U32*)(dst + (size_t)row * KP);
    int base = c16 * 8;
#pragma unroll
    for (int i = 0; i < 8; ++i) {
        o[base + i]      = hi[i];
        o[32 + base + i] = (mode == 0) ? lo[i] : hi[i];
        o[64 + base + i] = (mode == 0) ? hi[i] : lo[i];
    }
}

// ============================================================================
// Prepass B: split V into bf16 hi/lo arrays.
// ============================================================================
__global__ __launch_bounds__(256)
void vsplit_kernel(const float* __restrict__ V,
                   __nv_bfloat16* __restrict__ vhi, __nv_bfloat16* __restrict__ vlo) {
    int idx = blockIdx.x * blockDim.x + threadIdx.x;    // over float4s
    float4 v = ((const float4*)V)[idx];
    float h0 = bfhi(v.x), h1 = bfhi(v.y), h2 = bfhi(v.z), h3 = bfhi(v.w);
    ULL hv = (ULL)packbf(h0, h1) | ((ULL)packbf(h2, h3) << 32);
    ULL lv = (ULL)packbf(v.x - h0, v.y - h1) | ((ULL)packbf(v.z - h2, v.w - h3) << 32);
    ((ULL*)vhi)[idx] = hv;
    ((ULL*)vlo)[idx] = lv;
}

// ============================================================================
// Kernel 1: QK^T via mma.sync bf16 split (K'=192). 128x128 tile per CTA,
// 8 warps in 4(m) x 2(n), each warp 32x64. Epilogue fuses scale + mask.
// ============================================================================
#define QK_SA 200                 // padded smem row stride in bf16 (400B = 25*16B, odd)
#define QK_SMEM (2 * 128 * QK_SA * 2)

__global__ __launch_bounds__(256, 2)
void qk_mma_kernel(const int* __restrict__ mask, float* __restrict__ attn) {
    extern __shared__ __nv_bfloat16 smqk[];
    __nv_bfloat16* As = smqk;                  // [128][QK_SA]
    __nv_bfloat16* Bs = smqk + 128 * QK_SA;

    const int bh = blockIdx.z, b = bh >> 4;
    const int q0 = blockIdx.y * 128, k0 = blockIdx.x * 128;
    const int tid = threadIdx.x, lane = tid & 31, w = tid >> 5;
    const int wm = w >> 1, wn = w & 1;

    const uint4* Ag = (const uint4*)(g_qcat + ((size_t)bh * SS + q0) * KP);
    const uint4* Bg = (const uint4*)(g_kcat + ((size_t)bh * SS + k0) * KP);

#pragma unroll
    for (int t = 0; t < 12; ++t) {
        int idx = tid + t * 256;          // 0..3071
        int row = idx / 24, c = idx % 24; // 24 uint4 per row (192 bf16)
        *(uint4*)&As[row * QK_SA + c * 8] = Ag[row * 24 + c];
        *(uint4*)&Bs[row * QK_SA + c * 8] = Bg[row * 24 + c];
    }
    __syncthreads();

    float acc[2][8][4];
#pragma unroll
    for (int mt = 0; mt < 2; ++mt)
#pragma unroll
        for (int nt = 0; nt < 8; ++nt)
#pragma unroll
            for (int i = 0; i < 4; ++i) acc[mt][nt][i] = 0.f;

    const U32 aB = smem_u32(As), bB = smem_u32(Bs);
    U32 aAddr[2], bAddr[4];
#pragma unroll
    for (int mt = 0; mt < 2; ++mt)
        aAddr[mt] = aB + (U32)((wm * 32 + mt * 16 + (lane & 15)) * (QK_SA * 2)
                               + (((lane >> 4) << 3) << 1));
#pragma unroll
    for (int p = 0; p < 4; ++p)
        bAddr[p] = bB + (U32)((wn * 64 + p * 16 + (lane & 7) + ((lane >> 4) << 3)) * (QK_SA * 2)
                              + ((((lane >> 3) & 1) << 3) << 1));

#pragma unroll
    for (int ks = 0; ks < 12; ++ks) {
        U32 af[2][4], bf[8][2];
#pragma unroll
        for (int mt = 0; mt < 2; ++mt) ldsm_x4(af[mt], aAddr[mt] + ks * 32);
#pragma unroll
        for (int p = 0; p < 4; ++p) {
            U32 rr[4];
            ldsm_x4(rr, bAddr[p] + ks * 32);
            bf[2 * p][0] = rr[0]; bf[2 * p][1] = rr[1];
            bf[2 * p + 1][0] = rr[2]; bf[2 * p + 1][1] = rr[3];
        }
#pragma unroll
        for (int mt = 0; mt < 2; ++mt)
#pragma unroll
            for (int nt = 0; nt < 8; ++nt)
                mma16816(acc[mt][nt], af[mt], bf[nt]);
    }

    // epilogue: scale + mask, write fp32 scores
    const int lr = lane >> 2, lc = (lane & 3) * 2;
#pragma unroll
    for (int mt = 0; mt < 2; ++mt) {
#pragma unroll
        for (int half = 0; half < 2; ++half) {
            int qrow = q0 + wm * 32 + mt * 16 + lr + half * 8;
            const int* mrow = mask + ((size_t)b * SS + qrow) * SS + k0 + wn * 64 + lc;
            float* orow = attn + ((size_t)bh * SS + qrow) * SS + k0 + wn * 64 + lc;
#pragma unroll
            for (int nt = 0; nt < 8; ++nt) {
                int2 mk = *(const int2*)(mrow + nt * 8);
                float2 v;
                float c0 = acc[mt][nt][half * 2 + 0] * SCALE;
                float c1 = acc[mt][nt][half * 2 + 1] * SCALE;
                v.x = mk.x ? c0 : -1e9f;
                v.y = mk.y ? c1 : -1e9f;
                *(float2*)(orow + nt * 8) = v;
            }
        }
    }
}

// ============================================================================
// Kernel 2: in-place row softmax over 2048 elements. One CTA (128 thr) / row.
// ============================================================================
__global__ __launch_bounds__(128)
void softmax_kernel(float* __restrict__ attn) {
    const size_t row = blockIdx.x;
    float* p = attn + row * (size_t)SS;
    const int tid = threadIdx.x;

    float4 v[4];
#pragma unroll
    for (int t = 0; t < 4; ++t) v[t] = ((const float4*)p)[tid + t * 128];

    float m = -3.4e38f;
#pragma unroll
    for (int t = 0; t < 4; ++t)
        m = fmaxf(m, fmaxf(fmaxf(v[t].x, v[t].y), fmaxf(v[t].z, v[t].w)));
#pragma unroll
    for (int o = 16; o > 0; o >>= 1)
        m = fmaxf(m, __shfl_xor_sync(0xffffffffu, m, o));

    __shared__ float redm[4];
    __shared__ float reds[4];
    const int wid = tid >> 5, lid = tid & 31;
    if (lid == 0) redm[wid] = m;
    __syncthreads();
    m = fmaxf(fmaxf(redm[0], redm[1]), fmaxf(redm[2], redm[3]));

    float s = 0.f;
#pragma unroll
    for (int t = 0; t < 4; ++t) {
        v[t].x = __expf(v[t].x - m); v[t].y = __expf(v[t].y - m);
        v[t].z = __expf(v[t].z - m); v[t].w = __expf(v[t].w - m);
        s += (v[t].x + v[t].y) + (v[t].z + v[t].w);
    }
#pragma unroll
    for (int o = 16; o > 0; o >>= 1)
        s += __shfl_xor_sync(0xffffffffu, s, o);
    if (lid == 0) reds[wid] = s;
    __syncthreads();
    s = (reds[0] + reds[1]) + (reds[2] + reds[3]);

    const float inv = 1.0f / s;
#pragma unroll
    for (int t = 0; t < 4; ++t) {
        v[t].x *= inv; v[t].y *= inv; v[t].z *= inv; v[t].w *= inv;
        ((float4*)p)[tid + t * 128] = v[t];
    }
}

// ============================================================================
// Kernel 3: O = W @ V via mma.sync bf16 split. 128q x 64d tile per CTA,
// 8 warps in 4(m) x 2(n), warp 32x32. W split to hi/lo in-kernel; V pre-split.
// 3 passes: Whi*Vhi + Wlo*Vhi + Whi*Vlo.
// ============================================================================
#define PV_WS 72                   // padded smem stride bf16 (144B = 9*16B, odd)
#define PV_SMEM ((2 * 128 + 2 * 64) * PV_WS * 2)

__global__ __launch_bounds__(256, 2)
void pv_mma_kernel(const float* __restrict__ attn,
                   const __nv_bfloat16* __restrict__ vhi,
                   const __nv_bfloat16* __restrict__ vlo,
                   float* __restrict__ O) {
    extern __shared__ __nv_bfloat16 smpv[];
    __nv_bfloat16* Whi = smpv;                      // [128][72]
    __nv_bfloat16* Wlo = Whi + 128 * PV_WS;
    __nv_bfloat16* Vhs = Wlo + 128 * PV_WS;         // [64][72]
    __nv_bfloat16* Vls = Vhs + 64 * PV_WS;

    const int bh = blockIdx.y, q0 = blockIdx.x * 128;
    const int tid = threadIdx.x, lane = tid & 31, w = tid >> 5;
    const int wm = w >> 1, wn = w & 1;

    float acc[2][4][4];
#pragma unroll
    for (int mt = 0; mt < 2; ++mt)
#pragma unroll
        for (int nt = 0; nt < 4; ++nt)
#pragma unroll
            for (int i = 0; i < 4; ++i) acc[mt][nt][i] = 0.f;

    const U32 whiB = smem_u32(Whi), wloB = smem_u32(Wlo);
    const U32 vhiB = smem_u32(Vhs), vloB = smem_u32(Vls);
    U32 wAddrHi[2], wAddrLo[2], vAddrHi[2], vAddrLo[2];
#pragma unroll
    for (int mt = 0; mt < 2; ++mt) {
        U32 off = (U32)((wm * 32 + mt * 16 + (lane & 15)) * (PV_WS * 2)
                        + (((lane >> 4) << 3) << 1));
        wAddrHi[mt] = whiB + off;
        wAddrLo[mt] = wloB + off;
    }
#pragma unroll
    for (int p = 0; p < 2; ++p) {
        U32 off = (U32)(((lane & 7) + (((lane >> 3) & 1) << 3)) * (PV_WS * 2)
                        + ((wn * 32 + p * 16 + ((lane >> 4) << 3)) << 1));
        vAddrHi[p] = vhiB + off;
        vAddrLo[p] = vloB + off;
    }

    for (int kt = 0; kt < 32; ++kt) {
        // W float tile 128x64 -> hi/lo bf16 smem
#pragma unroll
        for (int t = 0; t < 8; ++t) {
            int idx = tid + t * 256;
            int row = idx >> 4, c4 = idx & 15;
            float4 wv = *(const float4*)(attn + ((size_t)bh * SS + q0 + row) * SS + kt * 64 + c4 * 4);
            float h0 = bfhi(wv.x), h1 = bfhi(wv.y), h2 = bfhi(wv.z), h3 = bfhi(wv.w);
            *(ULL*)&Whi[row * PV_WS + c4 * 4] =
                (ULL)packbf(h0, h1) | ((ULL)packbf(h2, h3) << 32);
            *(ULL*)&Wlo[row * PV_WS + c4 * 4] =
                (ULL)packbf(wv.x - h0, wv.y - h1) | ((ULL)packbf(wv.z - h2, wv.w - h3) << 32);
        }
        // V tiles 64x64 bf16 (pre-split)
#pragma unroll
        for (int t = 0; t < 2; ++t) {
            int idx = tid + t * 256;
            int row = idx >> 3, c = idx & 7;
            size_t g = ((size_t)bh * SS + kt * 64 + row) * DKK + c * 8;
            *(uint4*)&Vhs[row * PV_WS + c * 8] = *(const uint4*)(vhi + g);
            *(uint4*)&Vls[row * PV_WS + c * 8] = *(const uint4*)(vlo + g);
        }
        __syncthreads();

#pragma unroll
        for (int ks = 0; ks < 4; ++ks) {
            U32 ah[2][4], al[2][4], bh2[4][2], bl2[4][2];
#pragma unroll
            for (int mt = 0; mt < 2; ++mt) {
                ldsm_x4(ah[mt], wAddrHi[mt] + ks * 32);
                ldsm_x4(al[mt], wAddrLo[mt] + ks * 32);
            }
#pragma unroll
            for (int p = 0; p < 2; ++p) {
                U32 rr[4];
                ldsm_x4_t(rr, vAddrHi[p] + ks * 16 * (PV_WS * 2));
                bh2[2 * p][0] = rr[0]; bh2[2 * p][1] = rr[1];
                bh2[2 * p + 1][0] = rr[2]; bh2[2 * p + 1][1] = rr[3];
                ldsm_x4_t(rr, vAddrLo[p] + ks * 16 * (PV_WS * 2));
                bl2[2 * p][0] = rr[0]; bl2[2 * p][1] = rr[1];
                bl2[2 * p + 1][0] = rr[2]; bl2[2 * p + 1][1] = rr[3];
            }
            // pass-major ordering to break accumulator dependency chains
#pragma unroll
            for (int mt = 0; mt < 2; ++mt)
#pragma unroll
                for (int nt = 0; nt < 4; ++nt)
                    mma16816(acc[mt][nt], ah[mt], bh2[nt]);
#pragma unroll
            for (int mt = 0; mt < 2; ++mt)
#pragma unroll
                for (int nt = 0; nt < 4; ++nt)
                    mma16816(acc[mt][nt], al[mt], bh2[nt]);
#pragma unroll
            for (int mt = 0; mt < 2; ++mt)
#pragma unroll
                for (int nt = 0; nt < 4; ++nt)
                    mma16816(acc[mt][nt], ah[mt], bl2[nt]);
        }
        __syncthreads();
    }

    const int lr = lane >> 2, lc = (lane & 3) * 2;
#pragma unroll
    for (int mt = 0; mt < 2; ++mt) {
#pragma unroll
        for (int half = 0; half < 2; ++half) {
            int qrow = q0 + wm * 32 + mt * 16 + lr + half * 8;
            float* orow = O + ((size_t)bh * SS + qrow) * DKK + wn * 32 + lc;
#pragma unroll
            for (int nt = 0; nt < 4; ++nt) {
                float2 v;
                v.x = acc[mt][nt][half * 2 + 0];
                v.y = acc[mt][nt][half * 2 + 1];
                *(float2*)(orow + nt * 8) = v;
            }
        }
    }
}

// ============================================================================
// Launch
// ============================================================================
extern "C" void kernel_launch(void* const* d_in, const int* in_sizes, int n_in,
                              void* d_out, int out_size) {
    const float* Q    = (const float*)d_in[0];
    const float* K    = (const float*)d_in[1];
    const float* V    = (const float*)d_in[2];
    const int*   mask = (const int*)d_in[3];

    float* out = (float*)d_out;
    const long long O_ELEMS = (long long)BB * HH * SS * DKK;
    const long long A_ELEMS = (long long)BB * HH * SS * (long long)SS;

    float* Optr = out;
    float* attn;
    if ((long long)out_size >= O_ELEMS + A_ELEMS) {
        attn = out + O_ELEMS;
    } else {
        void* sp = nullptr;
        cudaGetSymbolAddress(&sp, g_attn_scratch);
        attn = (float*)sp;
    }

    __nv_bfloat16 *qcat, *kcat, *vhi, *vlo;
    { void* p; cudaGetSymbolAddress(&p, g_qcat); qcat = (__nv_bfloat16*)p; }
    { void* p; cudaGetSymbolAddress(&p, g_kcat); kcat = (__nv_bfloat16*)p; }
    { void* p; cudaGetSymbolAddress(&p, g_vhi);  vhi  = (__nv_bfloat16*)p; }
    { void* p; cudaGetSymbolAddress(&p, g_vlo);  vlo  = (__nv_bfloat16*)p; }

    cudaFuncSetAttribute(qk_mma_kernel, cudaFuncAttributeMaxDynamicSharedMemorySize, QK_SMEM);
    cudaFuncSetAttribute(pv_mma_kernel, cudaFuncAttributeMaxDynamicSharedMemorySize, PV_SMEM);

    const int nthr = BB * HH * SS * 4;
    split_kernel<<<(nthr + 255) / 256, 256>>>(Q, qcat, 0);
    split_kernel<<<(nthr + 255) / 256, 256>>>(K, kcat, 1);
    vsplit_kernel<<<(BB * HH * SS * DKK / 4 + 255) / 256, 256>>>(V, vhi, vlo);

    dim3 g1(SS / 128, SS / 128, BB * HH);
    qk_mma_kernel<<<g1, 256, QK_SMEM>>>(mask, attn);

    softmax_kernel<<<(unsigned)(BB * HH * SS), 128>>>(attn);

    dim3 g3(SS / 128, BB * HH);
    pv_mma_kernel<<<g3, 256, PV_SMEM>>>(attn, vhi, vlo, Optr);
}